// round 3
// baseline (speedup 1.0000x reference)
#include <cuda_runtime.h>

// SSIM loss, fused, f32x2-packed on ADJACENT column pairs (all LDS/STS 64-bit).
// Rank-2 window: K(i,j) = u(i) + u(j)  =>  conv = VGauss(HBox) + VBox(HGauss).

#define KS 11
#define TILE 32
#define HROWS 42          // TILE + 10 halo rows
#define RAWW 42           // raw tile width (with halo)
#define RAWS 44           // raw row stride (padded, even)
#define HSTR 34           // H-plane row stride (even for LDS.64)
#define HPLANE (HROWS*HSTR)   // 1428
#define NBLK 8192
#define IMG 512

__device__ float g_part[NBLK];
__device__ unsigned g_cnt;

typedef unsigned long long u64;

__device__ __forceinline__ u64 f2pack(float lo, float hi) {
    u64 r; asm("mov.b64 %0, {%1, %2};" : "=l"(r) : "f"(lo), "f"(hi)); return r;
}
__device__ __forceinline__ void f2unpack(float& lo, float& hi, u64 v) {
    asm("mov.b64 {%0, %1}, %2;" : "=f"(lo), "=f"(hi) : "l"(v));
}
__device__ __forceinline__ u64 add2(u64 a, u64 b) {
    u64 d; asm("add.rn.f32x2 %0, %1, %2;" : "=l"(d) : "l"(a), "l"(b)); return d;
}
__device__ __forceinline__ u64 mul2(u64 a, u64 b) {
    u64 d; asm("mul.rn.f32x2 %0, %1, %2;" : "=l"(d) : "l"(a), "l"(b)); return d;
}
__device__ __forceinline__ u64 fma2(u64 a, u64 b, u64 c) {
    u64 d; asm("fma.rn.f32x2 %0, %1, %2, %3;" : "=l"(d) : "l"(a), "l"(b), "l"(c)); return d;
}

extern __shared__ float smem[];

__global__ __launch_bounds__(256, 3)
void ssim_kernel(const float* __restrict__ img1, const float* __restrict__ img2,
                 const float* __restrict__ win, float* __restrict__ out) {
    float* sA = smem;                        // HROWS * RAWS
    float* sB = sA + HROWS*RAWS;             // HROWS * RAWS
    float* sH = sB + HROWS*RAWS;             // 10 planes * HPLANE
    __shared__ float sR[16];
    __shared__ float sWarp[8];
    __shared__ int   sLast;

    const int tid = threadIdx.x;
    const int n  = blockIdx.z;
    const int x0 = blockIdx.x * TILE;
    const int y0 = blockIdx.y * TILE;
    const float* p1 = img1 + (size_t)n * IMG * IMG;
    const float* p2 = img2 + (size_t)n * IMG * IMG;

    // ---- Phase 0: window row sums (for u recovery) ----
    if (tid < KS) {
        float s = 0.f;
        #pragma unroll
        for (int j = 0; j < KS; j++) s += win[tid*KS + j];
        sR[tid] = s;
    }

    // ---- Phase 1: stage raw tiles (with halo, zero-padded) ----
    for (int i = tid; i < HROWS*RAWW; i += 256) {
        int r = i / RAWW, c = i - r*RAWW;
        int gr = y0 - 5 + r, gc = x0 - 5 + c;
        float a = 0.f, b = 0.f;
        if (gr >= 0 && gr < IMG && gc >= 0 && gc < IMG) {
            int idx = gr*IMG + gc;
            a = p1[idx]; b = p2[idx];
        }
        sA[r*RAWS + c] = a;
        sB[r*RAWS + c] = b;
    }
    __syncthreads();

    // Recover u(i) = (R(i) - T/22)/11, keep packed only.
    u64 ug[KS];
    {
        float T = 0.f;
        #pragma unroll
        for (int i = 0; i < KS; i++) T += sR[i];
        float U = T * (1.f/22.f);
        #pragma unroll
        for (int i = 0; i < KS; i++) {
            float u = (sR[i] - U) * (1.f/11.f);
            ug[i] = f2pack(u, u);
        }
    }

    // ---- Phase 2: horizontal pass on adjacent column pairs (2c, 2c+1). ----
    for (int i = tid; i < HROWS*16; i += 256) {
        int r = i >> 4, c2 = (i & 15) << 1;
        const float2* ra = (const float2*)(sA + r*RAWS + c2);
        const float2* rb = (const float2*)(sB + r*RAWS + c2);
        float2 A[6], Bv[6];
        #pragma unroll
        for (int k = 0; k < 6; k++) { A[k] = ra[k]; Bv[k] = rb[k]; }

        u64 hb0=0,hb1=0,hb2=0,hb3=0,hb4=0;
        u64 hg0=0,hg1=0,hg2=0,hg3=0,hg4=0;
        #pragma unroll
        for (int j = 0; j < KS; j++) {
            u64 a, b;
            if ((j & 1) == 0) {
                a = f2pack(A[j>>1].x,  A[j>>1].y);
                b = f2pack(Bv[j>>1].x, Bv[j>>1].y);
            } else {
                a = f2pack(A[j>>1].y,  A[(j>>1)+1].x);
                b = f2pack(Bv[j>>1].y, Bv[(j>>1)+1].x);
            }
            u64 aa = mul2(a,a);
            u64 bb = mul2(b,b);
            u64 ab = mul2(a,b);
            hb0 = add2(hb0,a);  hg0 = fma2(ug[j],a,hg0);
            hb1 = add2(hb1,b);  hg1 = fma2(ug[j],b,hg1);
            hb2 = add2(hb2,aa); hg2 = fma2(ug[j],aa,hg2);
            hb3 = add2(hb3,bb); hg3 = fma2(ug[j],bb,hg3);
            hb4 = add2(hb4,ab); hg4 = fma2(ug[j],ab,hg4);
        }
        float* o = sH + r*HSTR + c2;
        *(u64*)(o + 0*HPLANE) = hb0;
        *(u64*)(o + 1*HPLANE) = hb1;
        *(u64*)(o + 2*HPLANE) = hb2;
        *(u64*)(o + 3*HPLANE) = hb3;
        *(u64*)(o + 4*HPLANE) = hb4;
        *(u64*)(o + 5*HPLANE) = hg0;
        *(u64*)(o + 6*HPLANE) = hg1;
        *(u64*)(o + 7*HPLANE) = hg2;
        *(u64*)(o + 8*HPLANE) = hg3;
        *(u64*)(o + 9*HPLANE) = hg4;
    }
    __syncthreads();

    // ---- Phase 3: vertical pass + SSIM. 2 adjacent cols x 2 rows / thread. ----
    const int c2 = (tid & 15) << 1;
    const int r0 = (tid >> 4) << 1;

    u64 cv[5][2];
    #pragma unroll
    for (int p = 0; p < 5; p++) {
        // VBox of HGauss (sliding, packed)
        u64 vb0, vb1;
        {
            const float* HG = sH + (5+p)*HPLANE + r0*HSTR + c2;
            u64 hg[12];
            #pragma unroll
            for (int k = 0; k < 12; k++) hg[k] = *(const u64*)(HG + k*HSTR);
            u64 s = hg[0];
            #pragma unroll
            for (int k = 1; k < 11; k++) s = add2(s, hg[k]);
            vb0 = s;
            const u64 m1 = f2pack(-1.f, -1.f);
            vb1 = fma2(m1, hg[0], add2(s, hg[11]));
        }
        // VGauss of HBox (direct 11-tap, packed)
        u64 vg0 = 0, vg1 = 0;
        {
            const float* HB = sH + p*HPLANE + r0*HSTR + c2;
            u64 hb[12];
            #pragma unroll
            for (int k = 0; k < 12; k++) hb[k] = *(const u64*)(HB + k*HSTR);
            #pragma unroll
            for (int t = 0; t < KS; t++) {
                vg0 = fma2(ug[t], hb[t],   vg0);
                vg1 = fma2(ug[t], hb[t+1], vg1);
            }
        }
        cv[p][0] = add2(vg0, vb0);
        cv[p][1] = add2(vg1, vb1);
    }

    const float DR = 1603.64208984375f - 1396.9390869140625f;
    const float C1s = (0.01f*DR)*(0.01f*DR);
    const float C2s = (0.03f*DR)*(0.03f*DR);
    const u64 c1v = f2pack(C1s, C1s);
    const u64 c2v = f2pack(C2s, C2s);
    const u64 two = f2pack(2.f, 2.f);
    const u64 m1  = f2pack(-1.f, -1.f);

    float lsum = 0.f;
    #pragma unroll
    for (int o = 0; o < 2; o++) {
        u64 mu1 = cv[0][o], mu2 = cv[1][o];
        u64 mu11 = mul2(mu1, mu1);
        u64 mu22 = mul2(mu2, mu2);
        u64 mu12 = mul2(mu1, mu2);
        u64 s11 = fma2(m1, mu11, cv[2][o]);
        u64 s22 = fma2(m1, mu22, cv[3][o]);
        u64 s12 = fma2(m1, mu12, cv[4][o]);
        u64 numA = fma2(two, mu12, c1v);
        u64 numB = fma2(two, s12, c2v);
        u64 num  = mul2(numA, numB);
        u64 denA = add2(add2(mu11, mu22), c1v);
        u64 denB = add2(add2(s11, s22), c2v);
        u64 den  = mul2(denA, denB);
        float nlo, nhi, dlo, dhi;
        f2unpack(nlo, nhi, num);
        f2unpack(dlo, dhi, den);
        lsum += __fdividef(nlo, dlo) + __fdividef(nhi, dhi);
    }

    // ---- Block reduction (deterministic partials) ----
    #pragma unroll
    for (int off = 16; off; off >>= 1)
        lsum += __shfl_down_sync(0xffffffffu, lsum, off);
    if ((tid & 31) == 0) sWarp[tid >> 5] = lsum;
    __syncthreads();
    if (tid == 0) {
        float s = 0.f;
        #pragma unroll
        for (int w = 0; w < 8; w++) s += sWarp[w];
        int bl = blockIdx.x + 16*blockIdx.y + 256*blockIdx.z;
        g_part[bl] = s;
        __threadfence();
        unsigned v = atomicAdd(&g_cnt, 1u);
        sLast = (v == NBLK - 1u);
    }
    __syncthreads();

    // ---- Last block: final deterministic reduction ----
    if (sLast) {
        __threadfence();
        float s = 0.f;
        for (int i = tid; i < NBLK; i += 256) s += g_part[i];
        #pragma unroll
        for (int off = 16; off; off >>= 1)
            s += __shfl_down_sync(0xffffffffu, s, off);
        if ((tid & 31) == 0) sWarp[tid >> 5] = s;
        __syncthreads();
        if (tid == 0) {
            float t = 0.f;
            #pragma unroll
            for (int w = 0; w < 8; w++) t += sWarp[w];
            out[0] = t * (1.f / (32.f * 512.f * 512.f));
            g_cnt = 0;   // reset for next graph replay
        }
    }
}

extern "C" void kernel_launch(void* const* d_in, const int* in_sizes, int n_in,
                              void* d_out, int out_size) {
    const float* preds  = (const float*)d_in[0];
    const float* target = (const float*)d_in[1];
    const float* window = (const float*)d_in[2];
    float* out = (float*)d_out;

    const int smem_bytes = (2*HROWS*RAWS + 10*HPLANE) * (int)sizeof(float); // 71904
    cudaFuncSetAttribute(ssim_kernel, cudaFuncAttributeMaxDynamicSharedMemorySize, smem_bytes);

    dim3 grid(IMG/TILE, IMG/TILE, 32);
    ssim_kernel<<<grid, 256, smem_bytes>>>(preds, target, window, out);
}

// round 4
// speedup vs baseline: 1.0920x; 1.0920x over previous
#include <cuda_runtime.h>
#include <cuda_fp16.h>

// SSIM loss, fused. Rank-2 window: K(i,j)=u(i)+u(j) => conv = VGauss(HBox)+VBox(HGauss).
// H-planes stored fp16, 10-plane interleaved 48B items; raw A/B interleaved float2.

#define KS 11
#define TILE 32
#define HROWS 42          // TILE + 10 halo rows
#define RAWW 42
#define RAWS 44           // float2 stride for interleaved raw
#define PITEM 12          // u32 per (row,colpair) plane item (10 half2 + 2 pad = 48B)
#define NBLK 8192
#define IMG 512

__device__ float g_part[NBLK];
__device__ unsigned g_cnt;

typedef unsigned long long u64;

__device__ __forceinline__ u64 f2pack(float lo, float hi) {
    u64 r; asm("mov.b64 %0, {%1, %2};" : "=l"(r) : "f"(lo), "f"(hi)); return r;
}
__device__ __forceinline__ void f2unpack(float& lo, float& hi, u64 v) {
    asm("mov.b64 {%0, %1}, %2;" : "=f"(lo), "=f"(hi) : "l"(v));
}
__device__ __forceinline__ u64 add2(u64 a, u64 b) {
    u64 d; asm("add.rn.f32x2 %0, %1, %2;" : "=l"(d) : "l"(a), "l"(b)); return d;
}
__device__ __forceinline__ u64 mul2(u64 a, u64 b) {
    u64 d; asm("mul.rn.f32x2 %0, %1, %2;" : "=l"(d) : "l"(a), "l"(b)); return d;
}
__device__ __forceinline__ u64 fma2(u64 a, u64 b, u64 c) {
    u64 d; asm("fma.rn.f32x2 %0, %1, %2, %3;" : "=l"(d) : "l"(a), "l"(b), "l"(c)); return d;
}
__device__ __forceinline__ unsigned h2u(__half2 h) { return *(unsigned*)&h; }
__device__ __forceinline__ __half2 u2h(unsigned u) { return *(__half2*)&u; }

__device__ __forceinline__ float ssim_px(float mu1, float mu2, float e11,
                                          float e22, float e12,
                                          float C1s, float C2s) {
    float mu11 = mu1*mu1, mu22 = mu2*mu2, mu12 = mu1*mu2;
    float s11 = e11 - mu11, s22 = e22 - mu22, s12 = e12 - mu12;
    float num = (2.f*mu12 + C1s) * (2.f*s12 + C2s);
    float den = (mu11 + mu22 + C1s) * (s11 + s22 + C2s);
    return __fdividef(num, den);
}

extern __shared__ float smem[];

__global__ __launch_bounds__(256, 4)
void ssim_kernel(const float* __restrict__ img1, const float* __restrict__ img2,
                 const float* __restrict__ win, float* __restrict__ out) {
    float2*   sAB = (float2*)smem;                       // HROWS*RAWS float2 (14784 B)
    unsigned* sP  = (unsigned*)(smem + HROWS*RAWS*2);    // HROWS*16*PITEM u32 (32256 B)
    __shared__ float sR[16];
    __shared__ float sWarp[8];
    __shared__ int   sLast;

    const int tid = threadIdx.x;
    const int n  = blockIdx.z;
    const int x0 = blockIdx.x * TILE;
    const int y0 = blockIdx.y * TILE;
    const float* p1 = img1 + (size_t)n * IMG * IMG;
    const float* p2 = img2 + (size_t)n * IMG * IMG;

    // ---- Phase 0: window row sums ----
    if (tid < KS) {
        float s = 0.f;
        #pragma unroll
        for (int j = 0; j < KS; j++) s += win[tid*KS + j];
        sR[tid] = s;
    }

    // ---- Phase 1: stage raw tiles interleaved (halo, zero-padded) ----
    for (int i = tid; i < HROWS*RAWW; i += 256) {
        int r = i / RAWW, c = i - r*RAWW;
        int gr = y0 - 5 + r, gc = x0 - 5 + c;
        float a = 0.f, b = 0.f;
        if (gr >= 0 && gr < IMG && gc >= 0 && gc < IMG) {
            int idx = gr*IMG + gc;
            a = p1[idx]; b = p2[idx];
        }
        sAB[r*RAWS + c] = make_float2(a, b);
    }
    __syncthreads();

    // Recover u(i) = (R(i) - T/22)/11 (scalar, packed per tap on the fly).
    float uu[KS];
    {
        float T = 0.f;
        #pragma unroll
        for (int i = 0; i < KS; i++) T += sR[i];
        float U = T * (1.f/22.f);
        #pragma unroll
        for (int i = 0; i < KS; i++) uu[i] = (sR[i] - U) * (1.f/11.f);
    }

    // ---- Phase 2: horizontal pass on adjacent column pairs; f32 accum,
    //      fp16 interleaved store (10 planes per 48B item). ----
    for (int i = tid; i < HROWS*16; i += 256) {
        int r = i >> 4, cp = i & 15;
        const float4* F4 = (const float4*)(sAB + r*RAWS + 2*cp);
        float4 F[6];
        #pragma unroll
        for (int m = 0; m < 6; m++) F[m] = F4[m];

        u64 hb0=0,hb1=0,hb2=0,hb3=0,hb4=0;
        u64 hg0=0,hg1=0,hg2=0,hg3=0,hg4=0;
        #pragma unroll
        for (int j = 0; j < KS; j++) {
            u64 a, b;
            if ((j & 1) == 0) {
                int m = j >> 1;
                a = f2pack(F[m].x, F[m].z);
                b = f2pack(F[m].y, F[m].w);
            } else {
                int m = j >> 1;
                a = f2pack(F[m].z, F[m+1].x);
                b = f2pack(F[m].w, F[m+1].y);
            }
            u64 ujj = f2pack(uu[j], uu[j]);
            u64 aa = mul2(a,a);
            u64 bb = mul2(b,b);
            u64 ab = mul2(a,b);
            hb0 = add2(hb0,a);  hg0 = fma2(ujj,a,hg0);
            hb1 = add2(hb1,b);  hg1 = fma2(ujj,b,hg1);
            hb2 = add2(hb2,aa); hg2 = fma2(ujj,aa,hg2);
            hb3 = add2(hb3,bb); hg3 = fma2(ujj,bb,hg3);
            hb4 = add2(hb4,ab); hg4 = fma2(ujj,ab,hg4);
        }
        unsigned q[10];
        {
            float lo, hi;
            f2unpack(lo,hi,hb0); q[0] = h2u(__floats2half2_rn(lo,hi));
            f2unpack(lo,hi,hb1); q[1] = h2u(__floats2half2_rn(lo,hi));
            f2unpack(lo,hi,hb2); q[2] = h2u(__floats2half2_rn(lo,hi));
            f2unpack(lo,hi,hb3); q[3] = h2u(__floats2half2_rn(lo,hi));
            f2unpack(lo,hi,hb4); q[4] = h2u(__floats2half2_rn(lo,hi));
            f2unpack(lo,hi,hg0); q[5] = h2u(__floats2half2_rn(lo,hi));
            f2unpack(lo,hi,hg1); q[6] = h2u(__floats2half2_rn(lo,hi));
            f2unpack(lo,hi,hg2); q[7] = h2u(__floats2half2_rn(lo,hi));
            f2unpack(lo,hi,hg3); q[8] = h2u(__floats2half2_rn(lo,hi));
            f2unpack(lo,hi,hg4); q[9] = h2u(__floats2half2_rn(lo,hi));
        }
        unsigned* o = sP + (r*16 + cp) * PITEM;
        *(uint4*)(o)     = make_uint4(q[0], q[1], q[2], q[3]);
        *(uint4*)(o + 4) = make_uint4(q[4], q[5], q[6], q[7]);
        *(uint2*)(o + 8) = make_uint2(q[8], q[9]);
    }
    __syncthreads();

    // ---- Phase 3: vertical pass in fp16; 2 adjacent cols x 2 rows / thread. ----
    const int cp = tid & 15;
    const int r0 = (tid >> 4) << 1;

    __half2 ugh[KS];
    #pragma unroll
    for (int t = 0; t < KS; t++) ugh[t] = __float2half2_rn(uu[t]);

    __half2 vg[5][2], vb[5][2];
    #pragma unroll
    for (int p = 0; p < 5; p++) {
        vg[p][0] = vg[p][1] = __float2half2_rn(0.f);
        vb[p][0] = vb[p][1] = __float2half2_rn(0.f);
    }

    #pragma unroll
    for (int k = 0; k < 12; k++) {
        const unsigned* o = sP + ((r0 + k)*16 + cp) * PITEM;
        uint4 q0 = *(const uint4*)(o);
        uint4 q1 = *(const uint4*)(o + 4);
        uint2 q2 = *(const uint2*)(o + 8);
        __half2 hb[5], hg[5];
        hb[0] = u2h(q0.x); hb[1] = u2h(q0.y); hb[2] = u2h(q0.z); hb[3] = u2h(q0.w);
        hb[4] = u2h(q1.x); hg[0] = u2h(q1.y); hg[1] = u2h(q1.z); hg[2] = u2h(q1.w);
        hg[3] = u2h(q2.x); hg[4] = u2h(q2.y);
        #pragma unroll
        for (int p = 0; p < 5; p++) {
            if (k <= 10) {
                vg[p][0] = __hfma2(ugh[k], hb[p], vg[p][0]);
                vb[p][0] = __hadd2(vb[p][0], hg[p]);
            }
            if (k >= 1) {
                vg[p][1] = __hfma2(ugh[k-1], hb[p], vg[p][1]);
                vb[p][1] = __hadd2(vb[p][1], hg[p]);
            }
        }
    }

    const float DR = 1603.64208984375f - 1396.9390869140625f;
    const float C1s = (0.01f*DR)*(0.01f*DR);
    const float C2s = (0.03f*DR)*(0.03f*DR);

    float lsum = 0.f;
    #pragma unroll
    for (int o = 0; o < 2; o++) {
        float2 c0 = __half22float2(__hadd2(vg[0][o], vb[0][o]));
        float2 c1 = __half22float2(__hadd2(vg[1][o], vb[1][o]));
        float2 c2 = __half22float2(__hadd2(vg[2][o], vb[2][o]));
        float2 c3 = __half22float2(__hadd2(vg[3][o], vb[3][o]));
        float2 c4 = __half22float2(__hadd2(vg[4][o], vb[4][o]));
        lsum += ssim_px(c0.x, c1.x, c2.x, c3.x, c4.x, C1s, C2s);
        lsum += ssim_px(c0.y, c1.y, c2.y, c3.y, c4.y, C1s, C2s);
    }

    // ---- Block reduction (deterministic partials) ----
    #pragma unroll
    for (int off = 16; off; off >>= 1)
        lsum += __shfl_down_sync(0xffffffffu, lsum, off);
    if ((tid & 31) == 0) sWarp[tid >> 5] = lsum;
    __syncthreads();
    if (tid == 0) {
        float s = 0.f;
        #pragma unroll
        for (int w = 0; w < 8; w++) s += sWarp[w];
        int bl = blockIdx.x + 16*blockIdx.y + 256*blockIdx.z;
        g_part[bl] = s;
        __threadfence();
        unsigned v = atomicAdd(&g_cnt, 1u);
        sLast = (v == NBLK - 1u);
    }
    __syncthreads();

    // ---- Last block: final deterministic reduction ----
    if (sLast) {
        __threadfence();
        float s = 0.f;
        for (int i = tid; i < NBLK; i += 256) s += g_part[i];
        #pragma unroll
        for (int off = 16; off; off >>= 1)
            s += __shfl_down_sync(0xffffffffu, s, off);
        if ((tid & 31) == 0) sWarp[tid >> 5] = s;
        __syncthreads();
        if (tid == 0) {
            float t = 0.f;
            #pragma unroll
            for (int w = 0; w < 8; w++) t += sWarp[w];
            out[0] = t * (1.f / (32.f * 512.f * 512.f));
            g_cnt = 0;   // reset for next graph replay
        }
    }
}

extern "C" void kernel_launch(void* const* d_in, const int* in_sizes, int n_in,
                              void* d_out, int out_size) {
    const float* preds  = (const float*)d_in[0];
    const float* target = (const float*)d_in[1];
    const float* window = (const float*)d_in[2];
    float* out = (float*)d_out;

    const int smem_bytes = HROWS*RAWS*8 + HROWS*16*PITEM*4;  // 14784 + 32256 = 47040
    cudaFuncSetAttribute(ssim_kernel, cudaFuncAttributeMaxDynamicSharedMemorySize, smem_bytes);

    dim3 grid(IMG/TILE, IMG/TILE, 32);
    ssim_kernel<<<grid, 256, smem_bytes>>>(preds, target, window, out);
}

// round 5
// speedup vs baseline: 1.4545x; 1.3320x over previous
#include <cuda_runtime.h>
#include <cuda_fp16.h>

// SSIM loss, fused, fp16 datapath. Rank-2 window: K(i,j)=u(i)+u(j)
//   => conv = VGauss(HBox) + VBox(HGauss).
// Raw pixels staged as half2 column-pairs: even taps are direct register
// operands, odd taps are one PRMT. H-planes fp16, 10-plane interleaved 48B.

#define KS 11
#define TILE 32
#define HROWS 42          // TILE + 10 halo rows
#define RAWW 42
#define RH2 22            // half2 pairs per raw row (21 used, padded)
#define PITEM 12          // u32 per (row,colpair) plane item (10 half2 + pad)
#define NBLK 8192
#define IMG 512

__device__ float g_part[NBLK];
__device__ unsigned g_cnt;

__device__ __forceinline__ unsigned h2u(__half2 h) { return *(unsigned*)&h; }
__device__ __forceinline__ __half2 u2h(unsigned u) { return *(__half2*)&u; }

// crossing pair: (v1.hi, v2.lo)
__device__ __forceinline__ __half2 hcross(__half2 v1, __half2 v2) {
    return u2h(__byte_perm(h2u(v1), h2u(v2), 0x5432));
}

__device__ __forceinline__ float ssim_px(float mu1, float mu2, float e11,
                                          float e22, float e12,
                                          float C1s, float C2s) {
    float mu11 = mu1*mu1, mu22 = mu2*mu2, mu12 = mu1*mu2;
    float s11 = e11 - mu11, s22 = e22 - mu22, s12 = e12 - mu12;
    float num = (2.f*mu12 + C1s) * (2.f*s12 + C2s);
    float den = (mu11 + mu22 + C1s) * (s11 + s22 + C2s);
    return __fdividef(num, den);
}

extern __shared__ unsigned smem_u[];

__global__ __launch_bounds__(256, 4)
void ssim_kernel(const float* __restrict__ img1, const float* __restrict__ img2,
                 const float* __restrict__ win, float* __restrict__ out) {
    unsigned* sAh = smem_u;                        // HROWS*RH2 half2 (3696 B)
    unsigned* sBh = sAh + HROWS*RH2;               // HROWS*RH2 half2 (3696 B)
    unsigned* sP  = sBh + HROWS*RH2;               // HROWS*16*PITEM (32256 B)
    __shared__ float sR[16];
    __shared__ float sWarp[8];
    __shared__ int   sLast;

    const int tid = threadIdx.x;
    const int n  = blockIdx.z;
    const int x0 = blockIdx.x * TILE;
    const int y0 = blockIdx.y * TILE;
    const float* p1 = img1 + (size_t)n * IMG * IMG;
    const float* p2 = img2 + (size_t)n * IMG * IMG;

    // ---- Phase 0: window row sums ----
    if (tid < KS) {
        float s = 0.f;
        #pragma unroll
        for (int j = 0; j < KS; j++) s += win[tid*KS + j];
        sR[tid] = s;
    }

    // ---- Phase 1: stage raw pixels as half2 column-pairs (halo, 0-padded) ----
    for (int i = tid; i < HROWS*21; i += 256) {
        int r = i / 21, k = i - r*21;
        int gr = y0 - 5 + r;
        int gc0 = x0 - 5 + 2*k;
        float a0=0.f, a1=0.f, b0=0.f, b1=0.f;
        if (gr >= 0 && gr < IMG) {
            const float* q1 = p1 + gr*IMG;
            const float* q2 = p2 + gr*IMG;
            if (gc0 >= 0 && gc0 < IMG)       { a0 = q1[gc0];   b0 = q2[gc0];   }
            if (gc0+1 >= 0 && gc0+1 < IMG)   { a1 = q1[gc0+1]; b1 = q2[gc0+1]; }
        }
        sAh[r*RH2 + k] = h2u(__floats2half2_rn(a0, a1));
        sBh[r*RH2 + k] = h2u(__floats2half2_rn(b0, b1));
    }
    __syncthreads();

    // Recover u(i) = (R(i) - T/22)/11 ; keep fp32 (for phase 3 ssim) + half2 dup.
    float uu[KS];
    __half2 ugh[KS];
    {
        float T = 0.f;
        #pragma unroll
        for (int i = 0; i < KS; i++) T += sR[i];
        float U = T * (1.f/22.f);
        #pragma unroll
        for (int i = 0; i < KS; i++) {
            uu[i] = (sR[i] - U) * (1.f/11.f);
            ugh[i] = __float2half2_rn(uu[i]);
        }
    }

    // ---- Phase 2: horizontal pass, half2, adjacent column pairs ----
    for (int i = tid; i < HROWS*16; i += 256) {
        int r = i >> 4, c = i & 15;
        const unsigned* pa = sAh + r*RH2 + c;
        const unsigned* pb = sBh + r*RH2 + c;
        __half2 VA[6], VB[6];
        #pragma unroll
        for (int t = 0; t < 6; t++) { VA[t] = u2h(pa[t]); VB[t] = u2h(pb[t]); }

        __half2 z = __float2half2_rn(0.f);
        __half2 hb0=z,hb1=z,hb2=z,hb3=z,hb4=z;
        __half2 hg0=z,hg1=z,hg2=z,hg3=z,hg4=z;
        #pragma unroll
        for (int j = 0; j < KS; j++) {
            __half2 va, vb;
            if ((j & 1) == 0) { va = VA[j>>1]; vb = VB[j>>1]; }
            else { va = hcross(VA[j>>1], VA[(j>>1)+1]);
                   vb = hcross(VB[j>>1], VB[(j>>1)+1]); }
            __half2 aa = __hmul2(va,va);
            __half2 bb = __hmul2(vb,vb);
            __half2 ab = __hmul2(va,vb);
            __half2 u = ugh[j];
            hb0 = __hadd2(hb0,va); hg0 = __hfma2(u,va,hg0);
            hb1 = __hadd2(hb1,vb); hg1 = __hfma2(u,vb,hg1);
            hb2 = __hadd2(hb2,aa); hg2 = __hfma2(u,aa,hg2);
            hb3 = __hadd2(hb3,bb); hg3 = __hfma2(u,bb,hg3);
            hb4 = __hadd2(hb4,ab); hg4 = __hfma2(u,ab,hg4);
        }
        unsigned* o = sP + (r*16 + c) * PITEM;
        *(uint4*)(o)     = make_uint4(h2u(hb0), h2u(hb1), h2u(hb2), h2u(hb3));
        *(uint4*)(o + 4) = make_uint4(h2u(hb4), h2u(hg0), h2u(hg1), h2u(hg2));
        *(uint2*)(o + 8) = make_uint2(h2u(hg3), h2u(hg4));
    }
    __syncthreads();

    // ---- Phase 3: vertical pass in fp16; 2 adjacent cols x 2 rows / thread ----
    const int cp = tid & 15;
    const int r0 = (tid >> 4) << 1;

    __half2 vg[5][2], vb[5][2];
    #pragma unroll
    for (int p = 0; p < 5; p++) {
        vg[p][0] = vg[p][1] = __float2half2_rn(0.f);
        vb[p][0] = vb[p][1] = __float2half2_rn(0.f);
    }

    #pragma unroll
    for (int k = 0; k < 12; k++) {
        const unsigned* o = sP + ((r0 + k)*16 + cp) * PITEM;
        uint4 q0 = *(const uint4*)(o);
        uint4 q1 = *(const uint4*)(o + 4);
        uint2 q2 = *(const uint2*)(o + 8);
        __half2 hb[5], hg[5];
        hb[0] = u2h(q0.x); hb[1] = u2h(q0.y); hb[2] = u2h(q0.z); hb[3] = u2h(q0.w);
        hb[4] = u2h(q1.x); hg[0] = u2h(q1.y); hg[1] = u2h(q1.z); hg[2] = u2h(q1.w);
        hg[3] = u2h(q2.x); hg[4] = u2h(q2.y);
        #pragma unroll
        for (int p = 0; p < 5; p++) {
            if (k <= 10) {
                vg[p][0] = __hfma2(ugh[k], hb[p], vg[p][0]);
                vb[p][0] = __hadd2(vb[p][0], hg[p]);
            }
            if (k >= 1) {
                vg[p][1] = __hfma2(ugh[k-1], hb[p], vg[p][1]);
                vb[p][1] = __hadd2(vb[p][1], hg[p]);
            }
        }
    }

    const float DR = 1603.64208984375f - 1396.9390869140625f;
    const float C1s = (0.01f*DR)*(0.01f*DR);
    const float C2s = (0.03f*DR)*(0.03f*DR);

    float lsum = 0.f;
    #pragma unroll
    for (int o = 0; o < 2; o++) {
        float2 c0 = __half22float2(__hadd2(vg[0][o], vb[0][o]));
        float2 c1 = __half22float2(__hadd2(vg[1][o], vb[1][o]));
        float2 c2 = __half22float2(__hadd2(vg[2][o], vb[2][o]));
        float2 c3 = __half22float2(__hadd2(vg[3][o], vb[3][o]));
        float2 c4 = __half22float2(__hadd2(vg[4][o], vb[4][o]));
        lsum += ssim_px(c0.x, c1.x, c2.x, c3.x, c4.x, C1s, C2s);
        lsum += ssim_px(c0.y, c1.y, c2.y, c3.y, c4.y, C1s, C2s);
    }

    // ---- Block reduction (deterministic partials) ----
    #pragma unroll
    for (int off = 16; off; off >>= 1)
        lsum += __shfl_down_sync(0xffffffffu, lsum, off);
    if ((tid & 31) == 0) sWarp[tid >> 5] = lsum;
    __syncthreads();
    if (tid == 0) {
        float s = 0.f;
        #pragma unroll
        for (int w = 0; w < 8; w++) s += sWarp[w];
        int bl = blockIdx.x + 16*blockIdx.y + 256*blockIdx.z;
        g_part[bl] = s;
        __threadfence();
        unsigned v = atomicAdd(&g_cnt, 1u);
        sLast = (v == NBLK - 1u);
    }
    __syncthreads();

    // ---- Last block: final deterministic reduction ----
    if (sLast) {
        __threadfence();
        float s = 0.f;
        for (int i = tid; i < NBLK; i += 256) s += g_part[i];
        #pragma unroll
        for (int off = 16; off; off >>= 1)
            s += __shfl_down_sync(0xffffffffu, s, off);
        if ((tid & 31) == 0) sWarp[tid >> 5] = s;
        __syncthreads();
        if (tid == 0) {
            float t = 0.f;
            #pragma unroll
            for (int w = 0; w < 8; w++) t += sWarp[w];
            out[0] = t * (1.f / (32.f * 512.f * 512.f));
            g_cnt = 0;   // reset for next graph replay
        }
    }
}

extern "C" void kernel_launch(void* const* d_in, const int* in_sizes, int n_in,
                              void* d_out, int out_size) {
    const float* preds  = (const float*)d_in[0];
    const float* target = (const float*)d_in[1];
    const float* window = (const float*)d_in[2];
    float* out = (float*)d_out;

    const int smem_bytes = (2*HROWS*RH2 + HROWS*16*PITEM) * 4;  // 39648
    cudaFuncSetAttribute(ssim_kernel, cudaFuncAttributeMaxDynamicSharedMemorySize, smem_bytes);

    dim3 grid(IMG/TILE, IMG/TILE, 32);
    ssim_kernel<<<grid, 256, smem_bytes>>>(preds, target, window, out);
}

// round 6
// speedup vs baseline: 1.6560x; 1.1385x over previous
#include <cuda_runtime.h>
#include <cuda_fp16.h>

// SSIM loss, fused, fp16 datapath, 32x64 tiles.
// Rank-2 window: K(i,j)=u(i)+u(j) => conv = VGauss(HBox) + VBox(HGauss).
// Phase 2: quad col-pair items with cached stats + sliding horizontal box.
// Phase 3: 4 output rows/thread with sliding vertical box.

#define KS 11
#define TW 32
#define TH 64
#define RR 74             // TH + 10 halo rows
#define RH2 22            // 21 used half2 per raw row, padded
#define PITEM 12          // u32 per (row,colpair) plane item (10 half2 + pad)
#define NBLK 4096
#define IMG 512

__device__ float g_part[NBLK];
__device__ unsigned g_cnt;

__device__ __forceinline__ unsigned h2u(__half2 h) { return *(unsigned*)&h; }
__device__ __forceinline__ __half2 u2h(unsigned u) { return *(__half2*)&u; }

// crossing pair: (v1.hi, v2.lo)
__device__ __forceinline__ __half2 hcross(__half2 v1, __half2 v2) {
    return u2h(__byte_perm(h2u(v1), h2u(v2), 0x5432));
}

__device__ __forceinline__ float ssim_px(float mu1, float mu2, float e11,
                                          float e22, float e12,
                                          float C1s, float C2s) {
    float mu11 = mu1*mu1, mu22 = mu2*mu2, mu12 = mu1*mu2;
    float s11 = e11 - mu11, s22 = e22 - mu22, s12 = e12 - mu12;
    float num = (2.f*mu12 + C1s) * (2.f*s12 + C2s);
    float den = (mu11 + mu22 + C1s) * (s11 + s22 + C2s);
    return __fdividef(num, den);
}

extern __shared__ unsigned smem_u[];

__global__ __launch_bounds__(256, 3)
void ssim_kernel(const float* __restrict__ img1, const float* __restrict__ img2,
                 const float* __restrict__ win, float* __restrict__ out) {
    unsigned* sAh = smem_u;                  // RR*RH2
    unsigned* sBh = sAh + RR*RH2;            // RR*RH2
    unsigned* sP  = sBh + RR*RH2;            // RR*16*PITEM
    __shared__ float sR[16];
    __shared__ float sWarp[8];
    __shared__ int   sLast;

    const int tid = threadIdx.x;
    const int n  = blockIdx.z;
    const int x0 = blockIdx.x * TW;
    const int y0 = blockIdx.y * TH;
    const float* p1 = img1 + (size_t)n * IMG * IMG;
    const float* p2 = img2 + (size_t)n * IMG * IMG;

    // ---- Phase 0: window row sums ----
    if (tid < KS) {
        float s = 0.f;
        #pragma unroll
        for (int j = 0; j < KS; j++) s += win[tid*KS + j];
        sR[tid] = s;
    }

    // ---- Phase 1: stage raw pixels as half2 column-pairs (halo, 0-padded) ----
    for (int i = tid; i < RR*21; i += 256) {
        int r = i / 21, k = i - r*21;
        int gr = y0 - 5 + r;
        int gc0 = x0 - 5 + 2*k;
        float a0=0.f, a1=0.f, b0=0.f, b1=0.f;
        if (gr >= 0 && gr < IMG) {
            const float* q1 = p1 + gr*IMG;
            const float* q2 = p2 + gr*IMG;
            if (gc0 >= 0 && gc0 < IMG)     { a0 = q1[gc0];   b0 = q2[gc0];   }
            if (gc0+1 >= 0 && gc0+1 < IMG) { a1 = q1[gc0+1]; b1 = q2[gc0+1]; }
        }
        sAh[r*RH2 + k] = h2u(__floats2half2_rn(a0, a1));
        sBh[r*RH2 + k] = h2u(__floats2half2_rn(b0, b1));
    }
    __syncthreads();

    // Recover u(i) = (R(i) - T/22)/11 as half2 duplicates.
    __half2 ugh[KS];
    {
        float T = 0.f;
        #pragma unroll
        for (int i = 0; i < KS; i++) T += sR[i];
        float U = T * (1.f/22.f);
        #pragma unroll
        for (int i = 0; i < KS; i++)
            ugh[i] = __float2half2_rn((sR[i] - U) * (1.f/11.f));
    }

    // ---- Phase 2: horizontal pass. Item = (row, quad of 4 col-pairs).
    //      Stats cached once; box slides across the quad; gauss direct. ----
    for (int i = tid; i < RR*4; i += 256) {
        int r = i >> 2, q = i & 3;
        const unsigned* pa = sAh + r*RH2 + 4*q;
        const unsigned* pb = sBh + r*RH2 + 4*q;
        __half2 PL[5][9];     // planes: a, b, aa, bb, ab over 9 raw pairs
        #pragma unroll
        for (int t = 0; t < 9; t++) {
            __half2 a = u2h(pa[t]), b = u2h(pb[t]);
            PL[0][t] = a; PL[1][t] = b;
            PL[2][t] = __hmul2(a,a);
            PL[3][t] = __hmul2(b,b);
            PL[4][t] = __hmul2(a,b);
        }
        // box init for first cp of the quad
        __half2 box[5];
        #pragma unroll
        for (int p = 0; p < 5; p++) {
            __half2 s = PL[p][0];
            #pragma unroll
            for (int t = 1; t < 6; t++) s = __hadd2(s, PL[p][t]);
            #pragma unroll
            for (int t = 0; t < 5; t++) s = __hadd2(s, hcross(PL[p][t], PL[p][t+1]));
            box[p] = s;
        }
        unsigned* orow = sP + (r*16 + 4*q)*PITEM;
        #pragma unroll
        for (int c = 0; c < 4; c++) {
            if (c > 0) {
                #pragma unroll
                for (int p = 0; p < 5; p++) {
                    __half2 s = box[p];
                    s = __hsub2(s, PL[p][c-1]);
                    s = __hsub2(s, hcross(PL[p][c-1], PL[p][c]));
                    s = __hadd2(s, hcross(PL[p][c+4], PL[p][c+5]));
                    s = __hadd2(s, PL[p][c+5]);
                    box[p] = s;
                }
            }
            __half2 g[5];
            #pragma unroll
            for (int p = 0; p < 5; p++) g[p] = __hmul2(ugh[0], PL[p][c]);
            #pragma unroll
            for (int j = 1; j < KS; j++) {
                #pragma unroll
                for (int p = 0; p < 5; p++) {
                    __half2 v = ((j & 1) == 0)
                        ? PL[p][c + (j>>1)]
                        : hcross(PL[p][c + (j>>1)], PL[p][c + (j>>1) + 1]);
                    g[p] = __hfma2(ugh[j], v, g[p]);
                }
            }
            unsigned* o = orow + c*PITEM;
            *(uint4*)(o)   = make_uint4(h2u(box[0]), h2u(box[1]), h2u(box[2]), h2u(box[3]));
            *(uint4*)(o+4) = make_uint4(h2u(box[4]), h2u(g[0]), h2u(g[1]), h2u(g[2]));
            *(uint2*)(o+8) = make_uint2(h2u(g[3]), h2u(g[4]));
        }
    }
    __syncthreads();

    // ---- Phase 3: vertical pass; 2 cols x 4 rows per thread.
    //      VBox slides; VGauss direct. ----
    const int cp = tid & 15;
    const int r0 = (tid >> 4) << 2;

    __half2 vg[5][4];
    __half2 vb[5][4];
    __half2 hgE[5][3];
    #pragma unroll
    for (int p = 0; p < 5; p++) {
        #pragma unroll
        for (int o = 0; o < 4; o++) {
            vg[p][o] = __float2half2_rn(0.f);
            vb[p][o] = __float2half2_rn(0.f);
        }
    }

    #pragma unroll
    for (int k = 0; k < 14; k++) {
        const unsigned* o = sP + ((r0 + k)*16 + cp) * PITEM;
        uint4 q0 = *(const uint4*)(o);
        uint4 q1 = *(const uint4*)(o + 4);
        uint2 q2 = *(const uint2*)(o + 8);
        __half2 hb[5], hg[5];
        hb[0] = u2h(q0.x); hb[1] = u2h(q0.y); hb[2] = u2h(q0.z); hb[3] = u2h(q0.w);
        hb[4] = u2h(q1.x); hg[0] = u2h(q1.y); hg[1] = u2h(q1.z); hg[2] = u2h(q1.w);
        hg[3] = u2h(q2.x); hg[4] = u2h(q2.y);

        if (k < 3) {
            #pragma unroll
            for (int p = 0; p < 5; p++) hgE[p][k] = hg[p];
        }
        if (k <= 10) {
            #pragma unroll
            for (int p = 0; p < 5; p++) vb[p][0] = __hadd2(vb[p][0], hg[p]);
        }
        if (k == 11) {
            #pragma unroll
            for (int p = 0; p < 5; p++)
                vb[p][1] = __hadd2(__hsub2(vb[p][0], hgE[p][0]), hg[p]);
        }
        if (k == 12) {
            #pragma unroll
            for (int p = 0; p < 5; p++)
                vb[p][2] = __hadd2(__hsub2(vb[p][1], hgE[p][1]), hg[p]);
        }
        if (k == 13) {
            #pragma unroll
            for (int p = 0; p < 5; p++)
                vb[p][3] = __hadd2(__hsub2(vb[p][2], hgE[p][2]), hg[p]);
        }
        #pragma unroll
        for (int o2 = 0; o2 < 4; o2++) {
            int t = k - o2;
            if (t >= 0 && t <= 10) {
                #pragma unroll
                for (int p = 0; p < 5; p++)
                    vg[p][o2] = __hfma2(ugh[t], hb[p], vg[p][o2]);
            }
        }
    }

    const float DR = 1603.64208984375f - 1396.9390869140625f;
    const float C1s = (0.01f*DR)*(0.01f*DR);
    const float C2s = (0.03f*DR)*(0.03f*DR);

    float lsum = 0.f;
    #pragma unroll
    for (int o = 0; o < 4; o++) {
        float2 c0 = __half22float2(__hadd2(vg[0][o], vb[0][o]));
        float2 c1 = __half22float2(__hadd2(vg[1][o], vb[1][o]));
        float2 c2 = __half22float2(__hadd2(vg[2][o], vb[2][o]));
        float2 c3 = __half22float2(__hadd2(vg[3][o], vb[3][o]));
        float2 c4 = __half22float2(__hadd2(vg[4][o], vb[4][o]));
        lsum += ssim_px(c0.x, c1.x, c2.x, c3.x, c4.x, C1s, C2s);
        lsum += ssim_px(c0.y, c1.y, c2.y, c3.y, c4.y, C1s, C2s);
    }

    // ---- Block reduction (deterministic partials) ----
    #pragma unroll
    for (int off = 16; off; off >>= 1)
        lsum += __shfl_down_sync(0xffffffffu, lsum, off);
    if ((tid & 31) == 0) sWarp[tid >> 5] = lsum;
    __syncthreads();
    if (tid == 0) {
        float s = 0.f;
        #pragma unroll
        for (int w = 0; w < 8; w++) s += sWarp[w];
        int bl = blockIdx.x + 16*blockIdx.y + 128*blockIdx.z;
        g_part[bl] = s;
        __threadfence();
        unsigned v = atomicAdd(&g_cnt, 1u);
        sLast = (v == NBLK - 1u);
    }
    __syncthreads();

    // ---- Last block: final deterministic reduction ----
    if (sLast) {
        __threadfence();
        float s = 0.f;
        for (int i = tid; i < NBLK; i += 256) s += g_part[i];
        #pragma unroll
        for (int off = 16; off; off >>= 1)
            s += __shfl_down_sync(0xffffffffu, s, off);
        if ((tid & 31) == 0) sWarp[tid >> 5] = s;
        __syncthreads();
        if (tid == 0) {
            float t = 0.f;
            #pragma unroll
            for (int w = 0; w < 8; w++) t += sWarp[w];
            out[0] = t * (1.f / (32.f * 512.f * 512.f));
            g_cnt = 0;   // reset for next graph replay
        }
    }
}

extern "C" void kernel_launch(void* const* d_in, const int* in_sizes, int n_in,
                              void* d_out, int out_size) {
    const float* preds  = (const float*)d_in[0];
    const float* target = (const float*)d_in[1];
    const float* window = (const float*)d_in[2];
    float* out = (float*)d_out;

    const int smem_bytes = (2*RR*RH2 + RR*16*PITEM) * 4;  // 69856
    cudaFuncSetAttribute(ssim_kernel, cudaFuncAttributeMaxDynamicSharedMemorySize, smem_bytes);

    dim3 grid(IMG/TW, IMG/TH, 32);
    ssim_kernel<<<grid, 256, smem_bytes>>>(preds, target, window, out);
}

// round 8
// speedup vs baseline: 1.9673x; 1.1880x over previous
#include <cuda_runtime.h>
#include <cuda_fp16.h>

// SSIM loss, fused, fp16 datapath, 32x64 tiles, 4 stat planes.
// Rank-2 window: K(i,j)=u(i)+u(j) => conv = VGauss(HBox) + VBox(HGauss).
// Planes: a, b, ab, (aa+bb)  [s11+s22 only ever appears summed in SSIM].
// H-plane store: cp-major, PITEM=12 u32 (8 used, 16B-aligned), row stride
// RRP=75 so phase-3 LDS.128 quarter-warps are bank-conflict-free
// (item stride 900 u32 == 4 mod 32 -> lanes cp=0..7 hit groups 0,4,...,28).

#define KS 11
#define TW 32
#define TH 64
#define RR 74             // TH + 10 halo rows
#define RRP 75            // padded row count for sP stride (bank spread)
#define RH2 22            // 21 used half2 per raw row, padded
#define PITEM 12          // u32 per (cp,row) item: 8 half2 planes + 4 pad
#define NBLK 4096
#define IMG 512

__device__ float g_part[NBLK];
__device__ unsigned g_cnt;

__device__ __forceinline__ unsigned h2u(__half2 h) { return *(unsigned*)&h; }
__device__ __forceinline__ __half2 u2h(unsigned u) { return *(__half2*)&u; }

// crossing pair: (v1.hi, v2.lo)
__device__ __forceinline__ __half2 hcross(__half2 v1, __half2 v2) {
    return u2h(__byte_perm(h2u(v1), h2u(v2), 0x5432));
}

extern __shared__ unsigned smem_u[];

__global__ __launch_bounds__(256, 3)
void ssim_kernel(const float* __restrict__ img1, const float* __restrict__ img2,
                 const float* __restrict__ win, float* __restrict__ out) {
    unsigned* sAh = smem_u;                  // RR*RH2
    unsigned* sBh = sAh + RR*RH2;            // RR*RH2
    unsigned* sP  = sBh + RR*RH2;            // 16 * RRP * PITEM (cp-major)
    __shared__ float sR[16];
    __shared__ float sWarp[8];
    __shared__ int   sLast;

    const int tid = threadIdx.x;
    const int n  = blockIdx.z;
    const int x0 = blockIdx.x * TW;
    const int y0 = blockIdx.y * TH;
    const float* p1 = img1 + (size_t)n * IMG * IMG;
    const float* p2 = img2 + (size_t)n * IMG * IMG;

    // ---- Phase 0: window row sums ----
    if (tid < KS) {
        float s = 0.f;
        #pragma unroll
        for (int j = 0; j < KS; j++) s += win[tid*KS + j];
        sR[tid] = s;
    }

    // ---- Phase 1: stage raw pixels as half2 column-pairs (halo, 0-padded) ----
    for (int i = tid; i < RR*21; i += 256) {
        int r = i / 21, k = i - r*21;
        int gr = y0 - 5 + r;
        int gc0 = x0 - 5 + 2*k;
        float a0=0.f, a1=0.f, b0=0.f, b1=0.f;
        if (gr >= 0 && gr < IMG) {
            const float* q1 = p1 + gr*IMG;
            const float* q2 = p2 + gr*IMG;
            if (gc0 >= 0 && gc0 < IMG)     { a0 = q1[gc0];   b0 = q2[gc0];   }
            if (gc0+1 >= 0 && gc0+1 < IMG) { a1 = q1[gc0+1]; b1 = q2[gc0+1]; }
        }
        sAh[r*RH2 + k] = h2u(__floats2half2_rn(a0, a1));
        sBh[r*RH2 + k] = h2u(__floats2half2_rn(b0, b1));
    }
    __syncthreads();

    // Recover u(i) = (R(i) - T/22)/11 as half2 duplicates.
    __half2 ugh[KS];
    {
        float T = 0.f;
        #pragma unroll
        for (int i = 0; i < KS; i++) T += sR[i];
        float U = T * (1.f/22.f);
        #pragma unroll
        for (int i = 0; i < KS; i++)
            ugh[i] = __float2half2_rn((sR[i] - U) * (1.f/11.f));
    }

    // ---- Phase 2: horizontal pass. Item = (row, quad of 4 col-pairs).
    //      4 planes: a, b, ab, aa+bb. Box slides across quad; gauss direct. ----
    for (int i = tid; i < RR*4; i += 256) {
        int r = i >> 2, q = i & 3;
        const unsigned* pa = sAh + r*RH2 + 4*q;
        const unsigned* pb = sBh + r*RH2 + 4*q;
        __half2 PL[4][9];     // a, b, ab, aa+bb over 9 raw pairs
        #pragma unroll
        for (int t = 0; t < 9; t++) {
            __half2 a = u2h(pa[t]), b = u2h(pb[t]);
            PL[0][t] = a; PL[1][t] = b;
            PL[2][t] = __hmul2(a,b);
            PL[3][t] = __hfma2(b, b, __hmul2(a,a));
        }
        // box init for first cp of the quad
        __half2 box[4];
        #pragma unroll
        for (int p = 0; p < 4; p++) {
            __half2 s = PL[p][0];
            #pragma unroll
            for (int t = 1; t < 6; t++) s = __hadd2(s, PL[p][t]);
            #pragma unroll
            for (int t = 0; t < 5; t++) s = __hadd2(s, hcross(PL[p][t], PL[p][t+1]));
            box[p] = s;
        }
        #pragma unroll
        for (int c = 0; c < 4; c++) {
            if (c > 0) {
                #pragma unroll
                for (int p = 0; p < 4; p++) {
                    __half2 s = box[p];
                    s = __hsub2(s, PL[p][c-1]);
                    s = __hsub2(s, hcross(PL[p][c-1], PL[p][c]));
                    s = __hadd2(s, hcross(PL[p][c+4], PL[p][c+5]));
                    s = __hadd2(s, PL[p][c+5]);
                    box[p] = s;
                }
            }
            __half2 g[4];
            #pragma unroll
            for (int p = 0; p < 4; p++) g[p] = __hmul2(ugh[0], PL[p][c]);
            #pragma unroll
            for (int j = 1; j < KS; j++) {
                #pragma unroll
                for (int p = 0; p < 4; p++) {
                    __half2 v = ((j & 1) == 0)
                        ? PL[p][c + (j>>1)]
                        : hcross(PL[p][c + (j>>1)], PL[p][c + (j>>1) + 1]);
                    g[p] = __hfma2(ugh[j], v, g[p]);
                }
            }
            // cp-major store: item (cp = 4q+c, row r)
            unsigned* o = sP + ((4*q + c)*RRP + r)*PITEM;
            *(uint4*)(o)   = make_uint4(h2u(box[0]), h2u(box[1]), h2u(box[2]), h2u(box[3]));
            *(uint4*)(o+4) = make_uint4(h2u(g[0]),   h2u(g[1]),   h2u(g[2]),   h2u(g[3]));
        }
    }
    __syncthreads();

    // ---- Phase 3: vertical pass; 2 cols x 4 rows per thread.
    //      VBox slides; VGauss direct. ----
    const int cp = tid & 15;
    const int r0 = (tid >> 4) << 2;
    const unsigned* base = sP + (cp*RRP + r0)*PITEM;

    __half2 vg[4][4];
    __half2 vb[4][4];
    __half2 hgE[4][3];
    #pragma unroll
    for (int p = 0; p < 4; p++) {
        #pragma unroll
        for (int o = 0; o < 4; o++) {
            vg[p][o] = __float2half2_rn(0.f);
            vb[p][o] = __float2half2_rn(0.f);
        }
    }

    #pragma unroll
    for (int k = 0; k < 14; k++) {
        const unsigned* o = base + k*PITEM;
        uint4 q0 = *(const uint4*)(o);
        uint4 q1 = *(const uint4*)(o + 4);
        __half2 hb[4], hg[4];
        hb[0] = u2h(q0.x); hb[1] = u2h(q0.y); hb[2] = u2h(q0.z); hb[3] = u2h(q0.w);
        hg[0] = u2h(q1.x); hg[1] = u2h(q1.y); hg[2] = u2h(q1.z); hg[3] = u2h(q1.w);

        if (k < 3) {
            #pragma unroll
            for (int p = 0; p < 4; p++) hgE[p][k] = hg[p];
        }
        if (k <= 10) {
            #pragma unroll
            for (int p = 0; p < 4; p++) vb[p][0] = __hadd2(vb[p][0], hg[p]);
        }
        if (k == 11) {
            #pragma unroll
            for (int p = 0; p < 4; p++)
                vb[p][1] = __hadd2(__hsub2(vb[p][0], hgE[p][0]), hg[p]);
        }
        if (k == 12) {
            #pragma unroll
            for (int p = 0; p < 4; p++)
                vb[p][2] = __hadd2(__hsub2(vb[p][1], hgE[p][1]), hg[p]);
        }
        if (k == 13) {
            #pragma unroll
            for (int p = 0; p < 4; p++)
                vb[p][3] = __hadd2(__hsub2(vb[p][2], hgE[p][2]), hg[p]);
        }
        #pragma unroll
        for (int o2 = 0; o2 < 4; o2++) {
            int t = k - o2;
            if (t >= 0 && t <= 10) {
                #pragma unroll
                for (int p = 0; p < 4; p++)
                    vg[p][o2] = __hfma2(ugh[t], hb[p], vg[p][o2]);
            }
        }
    }

    const float DR = 1603.64208984375f - 1396.9390869140625f;
    const float C1s = (0.01f*DR)*(0.01f*DR);
    const float C2s = (0.03f*DR)*(0.03f*DR);

    float lsum = 0.f;
    #pragma unroll
    for (int o = 0; o < 4; o++) {
        float2 c0 = __half22float2(__hadd2(vg[0][o], vb[0][o]));   // mu1
        float2 c1 = __half22float2(__hadd2(vg[1][o], vb[1][o]));   // mu2
        float2 c2 = __half22float2(__hadd2(vg[2][o], vb[2][o]));   // E[ab]
        float2 c3 = __half22float2(__hadd2(vg[3][o], vb[3][o]));   // E[aa+bb]
        {
            float mu11 = c0.x*c0.x, mu22 = c1.x*c1.x, mu12 = c0.x*c1.x;
            float s12 = c2.x - mu12;
            float sS  = c3.x - mu11 - mu22;
            float num = (2.f*mu12 + C1s) * (2.f*s12 + C2s);
            float den = (mu11 + mu22 + C1s) * (sS + C2s);
            lsum += __fdividef(num, den);
        }
        {
            float mu11 = c0.y*c0.y, mu22 = c1.y*c1.y, mu12 = c0.y*c1.y;
            float s12 = c2.y - mu12;
            float sS  = c3.y - mu11 - mu22;
            float num = (2.f*mu12 + C1s) * (2.f*s12 + C2s);
            float den = (mu11 + mu22 + C1s) * (sS + C2s);
            lsum += __fdividef(num, den);
        }
    }

    // ---- Block reduction (deterministic partials) ----
    #pragma unroll
    for (int off = 16; off; off >>= 1)
        lsum += __shfl_down_sync(0xffffffffu, lsum, off);
    if ((tid & 31) == 0) sWarp[tid >> 5] = lsum;
    __syncthreads();
    if (tid == 0) {
        float s = 0.f;
        #pragma unroll
        for (int w = 0; w < 8; w++) s += sWarp[w];
        int bl = blockIdx.x + 16*blockIdx.y + 128*blockIdx.z;
        g_part[bl] = s;
        __threadfence();
        unsigned v = atomicAdd(&g_cnt, 1u);
        sLast = (v == NBLK - 1u);
    }
    __syncthreads();

    // ---- Last block: final deterministic reduction ----
    if (sLast) {
        __threadfence();
        float s = 0.f;
        for (int i = tid; i < NBLK; i += 256) s += g_part[i];
        #pragma unroll
        for (int off = 16; off; off >>= 1)
            s += __shfl_down_sync(0xffffffffu, s, off);
        if ((tid & 31) == 0) sWarp[tid >> 5] = s;
        __syncthreads();
        if (tid == 0) {
            float t = 0.f;
            #pragma unroll
            for (int w = 0; w < 8; w++) t += sWarp[w];
            out[0] = t * (1.f / (32.f * 512.f * 512.f));
            g_cnt = 0;   // reset for next graph replay
        }
    }
}

extern "C" void kernel_launch(void* const* d_in, const int* in_sizes, int n_in,
                              void* d_out, int out_size) {
    const float* preds  = (const float*)d_in[0];
    const float* target = (const float*)d_in[1];
    const float* window = (const float*)d_in[2];
    float* out = (float*)d_out;

    const int smem_bytes = (2*RR*RH2 + 16*RRP*PITEM) * 4;  // 70624
    cudaFuncSetAttribute(ssim_kernel, cudaFuncAttributeMaxDynamicSharedMemorySize, smem_bytes);

    dim3 grid(IMG/TW, IMG/TH, 32);
    ssim_kernel<<<grid, 256, smem_bytes>>>(preds, target, window, out);
}

// round 9
// speedup vs baseline: 2.1242x; 1.0797x over previous
#include <cuda_runtime.h>
#include <cuda_fp16.h>

// SSIM loss, fused, fp16 datapath, 32x64 tiles, 4 stat planes, occ-4.
// Rank-2 window: K(i,j)=u(i)+u(j) => conv = VGauss(HBox) + VBox(HGauss).
// Planes: a, b, ab, (aa+bb). H-planes split into two cp-major arrays of
// 16B items (box / gauss), stride RRP=75 rows -> phase-3 LDS.128 is
// bank-conflict-free (item stride 300 u32 == 12 mod 32).

#define KS 11
#define TW 32
#define TH 64
#define RR 74             // TH + 10 halo rows
#define RRP 75            // padded row count for plane arrays
#define RH2 22            // 21 used half2 per raw row, padded
#define NBLK 4096
#define IMG 512

__device__ float g_part[NBLK];
__device__ unsigned g_cnt;

__device__ __forceinline__ unsigned h2u(__half2 h) { return *(unsigned*)&h; }
__device__ __forceinline__ __half2 u2h(unsigned u) { return *(__half2*)&u; }

// crossing pair: (v1.hi, v2.lo)
__device__ __forceinline__ __half2 hcross(__half2 v1, __half2 v2) {
    return u2h(__byte_perm(h2u(v1), h2u(v2), 0x5432));
}

extern __shared__ unsigned smem_u[];

__global__ __launch_bounds__(256, 4)
void ssim_kernel(const float* __restrict__ img1, const float* __restrict__ img2,
                 const float* __restrict__ win, float* __restrict__ out) {
    unsigned* sAh = smem_u;                  // RR*RH2
    unsigned* sBh = sAh + RR*RH2;            // RR*RH2
    unsigned* sPB = sBh + RR*RH2;            // 16*RRP*4  (box planes)
    unsigned* sPG = sPB + 16*RRP*4;          // 16*RRP*4  (gauss planes)
    __shared__ float sR[16];
    __shared__ float sWarp[8];
    __shared__ int   sLast;

    const int tid = threadIdx.x;
    const int n  = blockIdx.z;
    const int x0 = blockIdx.x * TW;
    const int y0 = blockIdx.y * TH;
    const float* p1 = img1 + (size_t)n * IMG * IMG;
    const float* p2 = img2 + (size_t)n * IMG * IMG;

    // ---- Phase 0: window row sums ----
    if (tid < KS) {
        float s = 0.f;
        #pragma unroll
        for (int j = 0; j < KS; j++) s += win[tid*KS + j];
        sR[tid] = s;
    }

    // ---- Phase 1: stage raw pixels as half2 column-pairs (halo, 0-padded) ----
    for (int i = tid; i < RR*21; i += 256) {
        int r = i / 21, k = i - r*21;
        int gr = y0 - 5 + r;
        int gc0 = x0 - 5 + 2*k;
        float a0=0.f, a1=0.f, b0=0.f, b1=0.f;
        if (gr >= 0 && gr < IMG) {
            const float* q1 = p1 + gr*IMG;
            const float* q2 = p2 + gr*IMG;
            if (gc0 >= 0 && gc0 < IMG)     { a0 = q1[gc0];   b0 = q2[gc0];   }
            if (gc0+1 >= 0 && gc0+1 < IMG) { a1 = q1[gc0+1]; b1 = q2[gc0+1]; }
        }
        sAh[r*RH2 + k] = h2u(__floats2half2_rn(a0, a1));
        sBh[r*RH2 + k] = h2u(__floats2half2_rn(b0, b1));
    }
    __syncthreads();

    // Recover u(i) = (R(i) - T/22)/11 as half2 duplicates.
    __half2 ugh[KS];
    {
        float T = 0.f;
        #pragma unroll
        for (int i = 0; i < KS; i++) T += sR[i];
        float U = T * (1.f/22.f);
        #pragma unroll
        for (int i = 0; i < KS; i++)
            ugh[i] = __float2half2_rn((sR[i] - U) * (1.f/11.f));
    }

    // ---- Phase 2: horizontal pass. Item = (row, quad of 4 col-pairs).
    //      4 planes: a, b, ab, aa+bb. Box slides across quad; gauss direct. ----
    for (int i = tid; i < RR*4; i += 256) {
        int r = i >> 2, q = i & 3;
        const unsigned* pa = sAh + r*RH2 + 4*q;
        const unsigned* pb = sBh + r*RH2 + 4*q;
        __half2 PL[4][9];     // a, b, ab, aa+bb over 9 raw pairs
        #pragma unroll
        for (int t = 0; t < 9; t++) {
            __half2 a = u2h(pa[t]), b = u2h(pb[t]);
            PL[0][t] = a; PL[1][t] = b;
            PL[2][t] = __hmul2(a,b);
            PL[3][t] = __hfma2(b, b, __hmul2(a,a));
        }
        // box init for first cp of the quad
        __half2 box[4];
        #pragma unroll
        for (int p = 0; p < 4; p++) {
            __half2 s = PL[p][0];
            #pragma unroll
            for (int t = 1; t < 6; t++) s = __hadd2(s, PL[p][t]);
            #pragma unroll
            for (int t = 0; t < 5; t++) s = __hadd2(s, hcross(PL[p][t], PL[p][t+1]));
            box[p] = s;
        }
        #pragma unroll
        for (int c = 0; c < 4; c++) {
            if (c > 0) {
                #pragma unroll
                for (int p = 0; p < 4; p++) {
                    __half2 s = box[p];
                    s = __hsub2(s, PL[p][c-1]);
                    s = __hsub2(s, hcross(PL[p][c-1], PL[p][c]));
                    s = __hadd2(s, hcross(PL[p][c+4], PL[p][c+5]));
                    s = __hadd2(s, PL[p][c+5]);
                    box[p] = s;
                }
            }
            __half2 g[4];
            #pragma unroll
            for (int p = 0; p < 4; p++) g[p] = __hmul2(ugh[0], PL[p][c]);
            #pragma unroll
            for (int j = 1; j < KS; j++) {
                #pragma unroll
                for (int p = 0; p < 4; p++) {
                    __half2 v = ((j & 1) == 0)
                        ? PL[p][c + (j>>1)]
                        : hcross(PL[p][c + (j>>1)], PL[p][c + (j>>1) + 1]);
                    g[p] = __hfma2(ugh[j], v, g[p]);
                }
            }
            int item = ((4*q + c)*RRP + r) * 4;
            *(uint4*)(sPB + item) = make_uint4(h2u(box[0]), h2u(box[1]), h2u(box[2]), h2u(box[3]));
            *(uint4*)(sPG + item) = make_uint4(h2u(g[0]),   h2u(g[1]),   h2u(g[2]),   h2u(g[3]));
        }
    }
    __syncthreads();

    // ---- Phase 3: vertical pass; 2 cols x 4 rows per thread.
    //      VBox: accumulate window 0, then slide via end-row reloads.
    //      VGauss: direct 11-tap x 4 outputs. ----
    const int cp = tid & 15;
    const int r0 = (tid >> 4) << 2;
    const int ibase = (cp*RRP + r0) * 4;

    __half2 vg[4][4];
    __half2 vb0[4];
    #pragma unroll
    for (int p = 0; p < 4; p++) {
        vb0[p] = __float2half2_rn(0.f);
        #pragma unroll
        for (int o = 0; o < 4; o++) vg[p][o] = __float2half2_rn(0.f);
    }

    #pragma unroll
    for (int k = 0; k < 14; k++) {
        uint4 qb = *(const uint4*)(sPB + ibase + k*4);
        __half2 hb[4];
        hb[0] = u2h(qb.x); hb[1] = u2h(qb.y); hb[2] = u2h(qb.z); hb[3] = u2h(qb.w);
        if (k <= 10) {
            uint4 qg = *(const uint4*)(sPG + ibase + k*4);
            vb0[0] = __hadd2(vb0[0], u2h(qg.x));
            vb0[1] = __hadd2(vb0[1], u2h(qg.y));
            vb0[2] = __hadd2(vb0[2], u2h(qg.z));
            vb0[3] = __hadd2(vb0[3], u2h(qg.w));
        }
        #pragma unroll
        for (int o2 = 0; o2 < 4; o2++) {
            int t = k - o2;
            if (t >= 0 && t <= 10) {
                #pragma unroll
                for (int p = 0; p < 4; p++)
                    vg[p][o2] = __hfma2(ugh[t], hb[p], vg[p][o2]);
            }
        }
    }

    // slide the box: vb[o] = vb[o-1] - hg[o-1] + hg[o+10]
    __half2 vb[4][4];
    {
        uint4 e0  = *(const uint4*)(sPG + ibase + 0*4);
        uint4 e1  = *(const uint4*)(sPG + ibase + 1*4);
        uint4 e2  = *(const uint4*)(sPG + ibase + 2*4);
        uint4 l11 = *(const uint4*)(sPG + ibase + 11*4);
        uint4 l12 = *(const uint4*)(sPG + ibase + 12*4);
        uint4 l13 = *(const uint4*)(sPG + ibase + 13*4);
        const unsigned* pe0 = (const unsigned*)&e0;
        const unsigned* pe1 = (const unsigned*)&e1;
        const unsigned* pe2 = (const unsigned*)&e2;
        const unsigned* pl11 = (const unsigned*)&l11;
        const unsigned* pl12 = (const unsigned*)&l12;
        const unsigned* pl13 = (const unsigned*)&l13;
        #pragma unroll
        for (int p = 0; p < 4; p++) {
            vb[p][0] = vb0[p];
            vb[p][1] = __hadd2(__hsub2(vb[p][0], u2h(pe0[p])), u2h(pl11[p]));
            vb[p][2] = __hadd2(__hsub2(vb[p][1], u2h(pe1[p])), u2h(pl12[p]));
            vb[p][3] = __hadd2(__hsub2(vb[p][2], u2h(pe2[p])), u2h(pl13[p]));
        }
    }

    const float DR = 1603.64208984375f - 1396.9390869140625f;
    const float C1s = (0.01f*DR)*(0.01f*DR);
    const float C2s = (0.03f*DR)*(0.03f*DR);

    float lsum = 0.f;
    #pragma unroll
    for (int o = 0; o < 4; o++) {
        float2 c0 = __half22float2(__hadd2(vg[0][o], vb[0][o]));   // mu1
        float2 c1 = __half22float2(__hadd2(vg[1][o], vb[1][o]));   // mu2
        float2 c2 = __half22float2(__hadd2(vg[2][o], vb[2][o]));   // E[ab]
        float2 c3 = __half22float2(__hadd2(vg[3][o], vb[3][o]));   // E[aa+bb]
        {
            float mu11 = c0.x*c0.x, mu22 = c1.x*c1.x, mu12 = c0.x*c1.x;
            float s12 = c2.x - mu12;
            float sS  = c3.x - mu11 - mu22;
            float num = (2.f*mu12 + C1s) * (2.f*s12 + C2s);
            float den = (mu11 + mu22 + C1s) * (sS + C2s);
            lsum += __fdividef(num, den);
        }
        {
            float mu11 = c0.y*c0.y, mu22 = c1.y*c1.y, mu12 = c0.y*c1.y;
            float s12 = c2.y - mu12;
            float sS  = c3.y - mu11 - mu22;
            float num = (2.f*mu12 + C1s) * (2.f*s12 + C2s);
            float den = (mu11 + mu22 + C1s) * (sS + C2s);
            lsum += __fdividef(num, den);
        }
    }

    // ---- Block reduction (deterministic partials) ----
    #pragma unroll
    for (int off = 16; off; off >>= 1)
        lsum += __shfl_down_sync(0xffffffffu, lsum, off);
    if ((tid & 31) == 0) sWarp[tid >> 5] = lsum;
    __syncthreads();
    if (tid == 0) {
        float s = 0.f;
        #pragma unroll
        for (int w = 0; w < 8; w++) s += sWarp[w];
        int bl = blockIdx.x + 16*blockIdx.y + 128*blockIdx.z;
        g_part[bl] = s;
        __threadfence();
        unsigned v = atomicAdd(&g_cnt, 1u);
        sLast = (v == NBLK - 1u);
    }
    __syncthreads();

    // ---- Last block: final deterministic reduction ----
    if (sLast) {
        __threadfence();
        float s = 0.f;
        for (int i = tid; i < NBLK; i += 256) s += g_part[i];
        #pragma unroll
        for (int off = 16; off; off >>= 1)
            s += __shfl_down_sync(0xffffffffu, s, off);
        if ((tid & 31) == 0) sWarp[tid >> 5] = s;
        __syncthreads();
        if (tid == 0) {
            float t = 0.f;
            #pragma unroll
            for (int w = 0; w < 8; w++) t += sWarp[w];
            out[0] = t * (1.f / (32.f * 512.f * 512.f));
            g_cnt = 0;   // reset for next graph replay
        }
    }
}

extern "C" void kernel_launch(void* const* d_in, const int* in_sizes, int n_in,
                              void* d_out, int out_size) {
    const float* preds  = (const float*)d_in[0];
    const float* target = (const float*)d_in[1];
    const float* window = (const float*)d_in[2];
    float* out = (float*)d_out;

    const int smem_bytes = (2*RR*RH2 + 2*16*RRP*4) * 4;  // 51424
    cudaFuncSetAttribute(ssim_kernel, cudaFuncAttributeMaxDynamicSharedMemorySize, smem_bytes);

    dim3 grid(IMG/TW, IMG/TH, 32);
    ssim_kernel<<<grid, 256, smem_bytes>>>(preds, target, window, out);
}